// round 10
// baseline (speedup 1.0000x reference)
#include <cuda_runtime.h>
#include <math.h>

#define FDIM 128
#define HDIM 32
#define NN_MAX 100000
#define NE_MAX 3200000
#define NGRAPH 512

// ---- scratch (no allocation allowed) ----
__device__ __align__(128) float g_tA[NN_MAX * HDIM];
__device__ __align__(128) float g_tB[NN_MAX * HDIM];
__device__ __align__(128) float g_pool[NGRAPH * HDIM];
__device__ __align__(128) int   g_deg[NN_MAX + 1];
__device__ __align__(128) int   g_off[NN_MAX + 1];
__device__ __align__(128) int   g_cursor[NN_MAX];
__device__ __align__(128) int   g_ecol[NE_MAX];
__device__ __align__(128) float g_ew[NE_MAX];

// ---------------------------------------------------------------------------
// CSR build 1: degree histogram
// ---------------------------------------------------------------------------
__global__ void hist_kernel(const int* __restrict__ row, int* __restrict__ deg, int E) {
    int e0 = (blockIdx.x * blockDim.x + threadIdx.x) * 4;
    if (e0 + 3 < E) {
        int4 r = *(const int4*)(row + e0);
        atomicAdd(&deg[r.x], 1);
        atomicAdd(&deg[r.y], 1);
        atomicAdd(&deg[r.z], 1);
        atomicAdd(&deg[r.w], 1);
    } else {
        for (int e = e0; e < E; e++) atomicAdd(&deg[row[e]], 1);
    }
}

// ---------------------------------------------------------------------------
// CSR build 2: exclusive scan (single block, 1024 threads)
// ---------------------------------------------------------------------------
__global__ void scan_kernel(const int* __restrict__ deg, int* __restrict__ off,
                            int* __restrict__ cursor, int N) {
    __shared__ int warp_sums[32];
    __shared__ int s_carry;
    int tid = threadIdx.x;
    int lane = tid & 31, wid = tid >> 5;
    if (tid == 0) s_carry = 0;
    __syncthreads();

    for (int base = 0; base < N; base += 1024) {
        int i = base + tid;
        int v = (i < N) ? deg[i] : 0;
        int x = v;
#pragma unroll
        for (int d = 1; d < 32; d <<= 1) {
            int y = __shfl_up_sync(0xffffffffu, x, d);
            if (lane >= d) x += y;
        }
        if (lane == 31) warp_sums[wid] = x;
        __syncthreads();
        if (wid == 0) {
            int ws = warp_sums[lane];
            int xs = ws;
#pragma unroll
            for (int d = 1; d < 32; d <<= 1) {
                int y = __shfl_up_sync(0xffffffffu, xs, d);
                if (lane >= d) xs += y;
            }
            warp_sums[lane] = xs - ws;
        }
        __syncthreads();
        int excl = s_carry + warp_sums[wid] + (x - v);
        if (i < N) { off[i] = excl; cursor[i] = excl; }
        __syncthreads();
        if (tid == 1023) s_carry = excl + v;
        __syncthreads();
    }
    if (threadIdx.x == 0) off[N] = s_carry;
}

// ---------------------------------------------------------------------------
// CSR build 3: scatter edges into row-grouped arrays
// ---------------------------------------------------------------------------
__global__ void scatter_kernel(const int* __restrict__ row, const int* __restrict__ col,
                               const float* __restrict__ w,
                               int* __restrict__ cursor,
                               int* __restrict__ ecol, float* __restrict__ ew, int E) {
    int e = blockIdx.x * blockDim.x + threadIdx.x;
    if (e >= E) return;
    int r = row[e];
    int pos = atomicAdd(&cursor[r], 1);
    ecol[pos] = col[e];
    ew[pos]   = w[e];
}

// ---------------------------------------------------------------------------
// GEMM1: t = x @ W1  ([N,128] @ [128,32]); warp=8 rows, 4-k blocking.
// ---------------------------------------------------------------------------
__global__ void gemm1_kernel(const float* __restrict__ x,
                             const float* __restrict__ W,
                             float* __restrict__ t, int N) {
    __shared__ float sW[FDIM * HDIM];
    __shared__ float sx[64 * FDIM];
    int tid = threadIdx.x;
    int warp = tid >> 5, lane = tid & 31;
    for (int i = tid; i < FDIM * HDIM; i += 256) sW[i] = W[i];

    for (long base = (long)blockIdx.x * 64; base < N; base += (long)gridDim.x * 64) {
        int nrows = (int)min((long)64, (long)N - base);
        __syncthreads();
        int nquads = nrows * (FDIM / 4);
        const float4* src = (const float4*)(x + base * FDIM);
        for (int i = tid; i < nquads; i += 256)
            ((float4*)sx)[i] = src[i];
        __syncthreads();

        int r0 = warp * 8;
        float a[8] = {0.f,0.f,0.f,0.f,0.f,0.f,0.f,0.f};
        const float* xb = sx + r0 * FDIM;
#pragma unroll 4
        for (int k = 0; k < FDIM; k += 4) {
            float w0 = sW[(k + 0) * HDIM + lane];
            float w1 = sW[(k + 1) * HDIM + lane];
            float w2 = sW[(k + 2) * HDIM + lane];
            float w3 = sW[(k + 3) * HDIM + lane];
#pragma unroll
            for (int r = 0; r < 8; r++) {
                float4 xq = *(const float4*)(xb + r * FDIM + k);
                a[r] += xq.x * w0 + xq.y * w1 + xq.z * w2 + xq.w * w3;
            }
        }
#pragma unroll
        for (int r = 0; r < 8; r++)
            if (r0 + r < nrows)
                t[(base + r0 + r) * HDIM + lane] = a[r];
    }
}

// ---------------------------------------------------------------------------
// Shared gather core: warp per node; 4 groups x 8 lanes; each group gathers
// one edge's float4 row-quarter; butterfly-reduce across groups at the end.
// Result valid in ALL lanes (channels 4*(lane&7) .. +3).
// ---------------------------------------------------------------------------
__device__ __forceinline__ float4 csr_gather(const int* __restrict__ off,
                                             const int* __restrict__ ecol,
                                             const float* __restrict__ ew,
                                             const float4* __restrict__ tin4,
                                             int n, int lane) {
    int grp = lane >> 3;     // 0..3  (edge sub-slot)
    int l   = lane & 7;      // 0..7  (row quarter)
    int s = off[n], e1 = off[n + 1];
    float4 a = make_float4(0.f, 0.f, 0.f, 0.f);

    int e = s;
    for (; e + 16 <= e1; e += 16) {   // 16 edges/iter, 4 gathers in flight
        int i0 = e + grp;
        int c0 = ecol[i0];      float w0 = ew[i0];
        int c1 = ecol[i0 + 4];  float w1 = ew[i0 + 4];
        int c2 = ecol[i0 + 8];  float w2 = ew[i0 + 8];
        int c3 = ecol[i0 + 12]; float w3 = ew[i0 + 12];
        float4 v0 = tin4[c0 * 8 + l];
        float4 v1 = tin4[c1 * 8 + l];
        float4 v2 = tin4[c2 * 8 + l];
        float4 v3 = tin4[c3 * 8 + l];
        a.x += w0*v0.x + w1*v1.x + w2*v2.x + w3*v3.x;
        a.y += w0*v0.y + w1*v1.y + w2*v2.y + w3*v3.y;
        a.z += w0*v0.z + w1*v1.z + w2*v2.z + w3*v3.z;
        a.w += w0*v0.w + w1*v1.w + w2*v2.w + w3*v3.w;
    }
    for (; e < e1; e += 4) {          // masked remainder, 4 edges/iter
        int i = e + grp;
        int c = 0; float wt = 0.f;
        if (i < e1) { c = ecol[i]; wt = ew[i]; }
        float4 v = tin4[c * 8 + l];
        a.x += wt * v.x; a.y += wt * v.y; a.z += wt * v.z; a.w += wt * v.w;
    }
#pragma unroll
    for (int d = 8; d <= 16; d <<= 1) {
        a.x += __shfl_xor_sync(0xffffffffu, a.x, d);
        a.y += __shfl_xor_sync(0xffffffffu, a.y, d);
        a.z += __shfl_xor_sync(0xffffffffu, a.z, d);
        a.w += __shfl_xor_sync(0xffffffffu, a.w, d);
    }
    return a;
}

__device__ __forceinline__ float4 elu4(float4 a) {
    a.x = a.x > 0.f ? a.x : (expf(a.x) - 1.f);
    a.y = a.y > 0.f ? a.y : (expf(a.y) - 1.f);
    a.z = a.z > 0.f ? a.z : (expf(a.z) - 1.f);
    a.w = a.w > 0.f ? a.w : (expf(a.w) - 1.f);
    return a;
}

// ---------------------------------------------------------------------------
// Fused layer: tout[n] = (elu(spmm(tin)[n] + b)) @ Wnext
// ---------------------------------------------------------------------------
__global__ void spmm_fused_kernel(const int* __restrict__ off,
                                  const int* __restrict__ ecol,
                                  const float* __restrict__ ew,
                                  const float* __restrict__ tin,
                                  const float* __restrict__ b,
                                  const float* __restrict__ W,
                                  float* __restrict__ tout, int N) {
    __shared__ float sW[HDIM * HDIM];
    __shared__ float sb[HDIM];
    int tid = threadIdx.x;
    for (int i = tid; i < HDIM * HDIM; i += blockDim.x) sW[i] = W[i];
    if (tid < HDIM) sb[tid] = b[tid];
    __syncthreads();

    int lane = tid & 31;
    int n = (blockIdx.x * blockDim.x + tid) >> 5;
    if (n >= N) return;

    float4 a = csr_gather(off, ecol, ew, (const float4*)tin, n, lane);
    int l = lane & 7;
    float4 vb = *(const float4*)(sb + 4 * l);
    a.x += vb.x; a.y += vb.y; a.z += vb.z; a.w += vb.w;
    a = elu4(a);

    // GEMM 32x32: out[lane] = sum_k h[k]*W[k][lane]; h[4q..4q+3] lives in lane q
    float o = 0.f;
#pragma unroll
    for (int q = 0; q < 8; q++) {
        float hx = __shfl_sync(0xffffffffu, a.x, q);
        float hy = __shfl_sync(0xffffffffu, a.y, q);
        float hz = __shfl_sync(0xffffffffu, a.z, q);
        float hw = __shfl_sync(0xffffffffu, a.w, q);
        o += hx * sW[(4*q+0) * HDIM + lane]
           + hy * sW[(4*q+1) * HDIM + lane]
           + hz * sW[(4*q+2) * HDIM + lane]
           + hw * sW[(4*q+3) * HDIM + lane];
    }
    tout[n * HDIM + lane] = o;
}

// ---------------------------------------------------------------------------
// Final layer fused with pool: pool[seg[n]] += elu(spmm(tin)[n] + b3)
// ---------------------------------------------------------------------------
__global__ void spmm_pool_kernel(const int* __restrict__ off,
                                 const int* __restrict__ ecol,
                                 const float* __restrict__ ew,
                                 const float* __restrict__ tin,
                                 const float* __restrict__ b,
                                 const int* __restrict__ seg,
                                 float* __restrict__ pool, int N) {
    __shared__ float sb[HDIM];
    int tid = threadIdx.x;
    if (tid < HDIM) sb[tid] = b[tid];
    __syncthreads();

    int lane = tid & 31;
    int n = (blockIdx.x * blockDim.x + tid) >> 5;
    if (n >= N) return;

    float4 a = csr_gather(off, ecol, ew, (const float4*)tin, n, lane);
    int l = lane & 7;
    float4 vb = *(const float4*)(sb + 4 * l);
    a.x += vb.x; a.y += vb.y; a.z += vb.z; a.w += vb.w;
    a = elu4(a);

    if (lane < 8) {
        float4* dst = (float4*)(pool + seg[n] * HDIM) + l;
        asm volatile("red.global.add.v4.f32 [%0], {%1,%2,%3,%4};"
                     :: "l"(__cvta_generic_to_global(dst)),
                        "f"(a.x), "f"(a.y), "f"(a.z), "f"(a.w)
                     : "memory");
    }
}

// ---------------------------------------------------------------------------
// MLP head
// ---------------------------------------------------------------------------
__global__ void mlp_kernel(const float* __restrict__ pool,
                           const float* __restrict__ W1, const float* __restrict__ b1,
                           const float* __restrict__ W2, const float* __restrict__ b2,
                           const float* __restrict__ W3, const float* __restrict__ b3,
                           float* __restrict__ out) {
    __shared__ float sW1[32 * 64], sW2[64 * 32], sW3[32], sb1[64], sb2[32];
    int tid = threadIdx.x;
    for (int i = tid; i < 2048; i += blockDim.x) { sW1[i] = W1[i]; sW2[i] = W2[i]; }
    if (tid < 64) sb1[tid] = b1[tid];
    if (tid < 32) { sW3[tid] = W3[tid]; sb2[tid] = b2[tid]; }
    __syncthreads();

    int g = blockIdx.x * blockDim.x + tid;
    if (g >= NGRAPH) return;
    float in[32];
#pragma unroll
    for (int c = 0; c < 32; c++) in[c] = pool[g * 32 + c];
    float h2[32];
#pragma unroll
    for (int c = 0; c < 32; c++) h2[c] = sb2[c];
    for (int j = 0; j < 64; j++) {
        float t = sb1[j];
#pragma unroll
        for (int c = 0; c < 32; c++) t += in[c] * sW1[c * 64 + j];
        t = fmaxf(t, 0.f);
#pragma unroll
        for (int c = 0; c < 32; c++) h2[c] += t * sW2[j * 32 + c];
    }
    float o = b3[0];
#pragma unroll
    for (int c = 0; c < 32; c++) o += fmaxf(h2[c], 0.f) * sW3[c];
    out[g] = 1.f / (1.f + expf(-o));
}

// ---------------------------------------------------------------------------
extern "C" void kernel_launch(void* const* d_in, const int* in_sizes, int n_in,
                              void* d_out, int out_size) {
    const float* x   = (const float*)d_in[0];
    const int*   ei  = (const int*)  d_in[1];
    const float* ew  = (const float*)d_in[2];
    const int*   seg = (const int*)  d_in[3];
    const float* W1  = (const float*)d_in[4];
    const float* b1  = (const float*)d_in[5];
    const float* W2  = (const float*)d_in[6];
    const float* b2  = (const float*)d_in[7];
    const float* W3  = (const float*)d_in[8];
    const float* b3  = (const float*)d_in[9];
    const float* Wd1 = (const float*)d_in[10];
    const float* bd1 = (const float*)d_in[11];
    const float* Wd2 = (const float*)d_in[12];
    const float* bd2 = (const float*)d_in[13];
    const float* Wd3 = (const float*)d_in[14];
    const float* bd3 = (const float*)d_in[15];
    float* out = (float*)d_out;

    int N = in_sizes[0] / FDIM;
    int E = in_sizes[1] / 2;
    const int* row = ei;
    const int* col = ei + E;

    float *tA, *tB, *pool, *gew;
    int *deg, *off, *cursor, *gecol;
    cudaGetSymbolAddress((void**)&tA,     g_tA);
    cudaGetSymbolAddress((void**)&tB,     g_tB);
    cudaGetSymbolAddress((void**)&pool,   g_pool);
    cudaGetSymbolAddress((void**)&deg,    g_deg);
    cudaGetSymbolAddress((void**)&off,    g_off);
    cudaGetSymbolAddress((void**)&cursor, g_cursor);
    cudaGetSymbolAddress((void**)&gecol,  g_ecol);
    cudaGetSymbolAddress((void**)&gew,    g_ew);

    int warpBlocks = (N * 32 + 255) / 256;
    int gemm1Blocks = (N + 63) / 64;

    // ---- CSR build (amortized over 3 layers) ----
    cudaMemsetAsync(deg, 0, (size_t)(N + 1) * sizeof(int));
    hist_kernel<<<(E / 4 + 255) / 256 + 1, 256>>>(row, deg, E);
    scan_kernel<<<1, 1024>>>(deg, off, cursor, N);
    scatter_kernel<<<(E + 255) / 256, 256>>>(row, col, ew, cursor, gecol, gew, E);

    // ---- projection + fused GCN layers ----
    gemm1_kernel<<<gemm1Blocks, 256>>>(x, W1, tA, N);
    spmm_fused_kernel<<<warpBlocks, 256>>>(off, gecol, gew, tA, b1, W2, tB, N);
    spmm_fused_kernel<<<warpBlocks, 256>>>(off, gecol, gew, tB, b2, W3, tA, N);

    // ---- final layer + pool + head ----
    cudaMemsetAsync(pool, 0, (size_t)NGRAPH * HDIM * sizeof(float));
    spmm_pool_kernel<<<warpBlocks, 256>>>(off, gecol, gew, tA, b3, seg, pool, N);
    mlp_kernel<<<2, 256>>>(pool, Wd1, bd1, Wd2, bd2, Wd3, bd3, out);
}

// round 14
// speedup vs baseline: 1.2137x; 1.2137x over previous
#include <cuda_runtime.h>
#include <math.h>

#define FDIM 128
#define HDIM 32
#define NN_MAX 100000
#define NE_MAX 3200000
#define NGRAPH 512

// ---- scratch (no allocation allowed) ----
__device__ __align__(128) float g_tA[NN_MAX * HDIM];
__device__ __align__(128) float g_tB[NN_MAX * HDIM];
__device__ __align__(128) float g_pool[NGRAPH * HDIM];
__device__ __align__(128) int   g_deg[NN_MAX + 1];
__device__ __align__(128) int   g_off[NN_MAX + 1];
__device__ __align__(128) int   g_cursor[NN_MAX];
__device__ __align__(128) int   g_bsum[256];
__device__ __align__(128) int2  g_edge[NE_MAX];      // {col, float bits}

// ---------------------------------------------------------------------------
// CSR build 1: degree histogram
// ---------------------------------------------------------------------------
__global__ void hist_kernel(const int* __restrict__ row, int* __restrict__ deg, int E) {
    int e0 = (blockIdx.x * blockDim.x + threadIdx.x) * 4;
    if (e0 + 3 < E) {
        int4 r = *(const int4*)(row + e0);
        atomicAdd(&deg[r.x], 1);
        atomicAdd(&deg[r.y], 1);
        atomicAdd(&deg[r.z], 1);
        atomicAdd(&deg[r.w], 1);
    } else {
        for (int e = e0; e < E; e++) atomicAdd(&deg[row[e]], 1);
    }
}

// ---------------------------------------------------------------------------
// CSR build 2a: per-block exclusive scan (1024/block) + block sums
// ---------------------------------------------------------------------------
__global__ void scan1_kernel(const int* __restrict__ deg, int* __restrict__ off,
                             int* __restrict__ bsum, int N) {
    __shared__ int ws[32];
    int tid = threadIdx.x, lane = tid & 31, wid = tid >> 5;
    int i = blockIdx.x * 1024 + tid;
    int v = (i < N) ? deg[i] : 0;
    int x = v;
#pragma unroll
    for (int d = 1; d < 32; d <<= 1) {
        int y = __shfl_up_sync(0xffffffffu, x, d);
        if (lane >= d) x += y;
    }
    if (lane == 31) ws[wid] = x;
    __syncthreads();
    if (wid == 0) {
        int s = ws[lane];
        int xs = s;
#pragma unroll
        for (int d = 1; d < 32; d <<= 1) {
            int y = __shfl_up_sync(0xffffffffu, xs, d);
            if (lane >= d) xs += y;
        }
        ws[lane] = xs - s;
    }
    __syncthreads();
    int excl = ws[wid] + (x - v);
    if (i < N) off[i] = excl;
    if (tid == 1023) bsum[blockIdx.x] = excl + v;
}

// ---------------------------------------------------------------------------
// CSR build 2b: scan the block sums (single 128-thread block, nb <= 128)
// ---------------------------------------------------------------------------
__global__ void scan2_kernel(int* __restrict__ bsum, int nb, int* __restrict__ offN) {
    __shared__ int ws[4];
    int tid = threadIdx.x, lane = tid & 31, wid = tid >> 5;
    int v = (tid < nb) ? bsum[tid] : 0;
    int x = v;
#pragma unroll
    for (int d = 1; d < 32; d <<= 1) {
        int y = __shfl_up_sync(0xffffffffu, x, d);
        if (lane >= d) x += y;
    }
    if (lane == 31) ws[wid] = x;
    __syncthreads();
    int add = 0;
#pragma unroll
    for (int j = 0; j < 4; j++)
        if (j < wid) add += ws[j];
    int excl = add + (x - v);
    if (tid < nb) bsum[tid] = excl;
    if (tid == 127) *offN = excl + v;    // grand total (padded v = 0)
}

// ---------------------------------------------------------------------------
// CSR build 2c: add block bases; produce cursor copy
// ---------------------------------------------------------------------------
__global__ void scan3_kernel(int* __restrict__ off, const int* __restrict__ bsum,
                             int* __restrict__ cursor, int N) {
    int i = blockIdx.x * 1024 + threadIdx.x;
    if (i < N) {
        int o = off[i] + bsum[blockIdx.x];
        off[i] = o;
        cursor[i] = o;
    }
}

// ---------------------------------------------------------------------------
// CSR build 3: scatter edges (interleaved int2 {col, w}) — one ST.64/edge
// ---------------------------------------------------------------------------
__global__ void scatter_kernel(const int* __restrict__ row, const int* __restrict__ col,
                               const float* __restrict__ w,
                               int* __restrict__ cursor, int2* __restrict__ edge, int E) {
    int e = blockIdx.x * blockDim.x + threadIdx.x;
    if (e >= E) return;
    int r = row[e];
    int pos = atomicAdd(&cursor[r], 1);
    edge[pos] = make_int2(col[e], __float_as_int(w[e]));
}

// ---------------------------------------------------------------------------
// GEMM1: t = x @ W1  ([N,128] @ [128,32])
// 32-row tile (33KB smem -> 6 blocks/SM); W transposed+padded in smem so each
// lane reads its 4 W values with ONE conflict-free LDS.128 per 4-k step.
// ---------------------------------------------------------------------------
#define WPAD 132
__global__ void gemm1_kernel(const float* __restrict__ x,
                             const float* __restrict__ W,
                             float* __restrict__ t, int N) {
    __shared__ float sWT[HDIM * WPAD];   // [c][k] padded: 16.9 KB
    __shared__ float sx[32 * FDIM];      // 16 KB
    int tid = threadIdx.x;
    int warp = tid >> 5, lane = tid & 31;
    for (int i = tid; i < FDIM * HDIM; i += 256) {
        int k = i >> 5, c = i & 31;      // W[k][c]
        sWT[c * WPAD + k] = W[i];
    }

    for (long base = (long)blockIdx.x * 32; base < N; base += (long)gridDim.x * 32) {
        int nrows = (int)min((long)32, (long)N - base);
        __syncthreads();
        int nquads = nrows * (FDIM / 4);
        const float4* src = (const float4*)(x + base * FDIM);
        for (int i = tid; i < nquads; i += 256)
            ((float4*)sx)[i] = src[i];
        __syncthreads();

        int r0 = warp * 4;
        float a[4] = {0.f, 0.f, 0.f, 0.f};
        const float* xb = sx + r0 * FDIM;
        const float* wt = sWT + lane * WPAD;
#pragma unroll 8
        for (int k = 0; k < FDIM; k += 4) {
            float4 wq = *(const float4*)(wt + k);
#pragma unroll
            for (int r = 0; r < 4; r++) {
                float4 xq = *(const float4*)(xb + r * FDIM + k);
                a[r] += xq.x * wq.x + xq.y * wq.y + xq.z * wq.z + xq.w * wq.w;
            }
        }
#pragma unroll
        for (int r = 0; r < 4; r++)
            if (r0 + r < nrows)
                t[(base + r0 + r) * HDIM + lane] = a[r];
    }
}

// ---------------------------------------------------------------------------
// Gather core: warp per node; 4 groups x 8 lanes; interleaved int2 edges.
// Result valid in ALL lanes (channels 4*(lane&7) .. +3).
// ---------------------------------------------------------------------------
__device__ __forceinline__ float4 csr_gather(const int* __restrict__ off,
                                             const int2* __restrict__ edge,
                                             const float4* __restrict__ tin4,
                                             int n, int lane) {
    int grp = lane >> 3;     // 0..3  (edge sub-slot)
    int l   = lane & 7;      // 0..7  (row quarter)
    int s = off[n], e1 = off[n + 1];
    float4 a = make_float4(0.f, 0.f, 0.f, 0.f);

    int e = s;
    for (; e + 16 <= e1; e += 16) {   // 16 edges/iter, 4 gathers in flight
        int i0 = e + grp;
        int2 E0 = edge[i0];
        int2 E1 = edge[i0 + 4];
        int2 E2 = edge[i0 + 8];
        int2 E3 = edge[i0 + 12];
        float w0 = __int_as_float(E0.y);
        float w1 = __int_as_float(E1.y);
        float w2 = __int_as_float(E2.y);
        float w3 = __int_as_float(E3.y);
        float4 v0 = tin4[E0.x * 8 + l];
        float4 v1 = tin4[E1.x * 8 + l];
        float4 v2 = tin4[E2.x * 8 + l];
        float4 v3 = tin4[E3.x * 8 + l];
        a.x += w0*v0.x + w1*v1.x + w2*v2.x + w3*v3.x;
        a.y += w0*v0.y + w1*v1.y + w2*v2.y + w3*v3.y;
        a.z += w0*v0.z + w1*v1.z + w2*v2.z + w3*v3.z;
        a.w += w0*v0.w + w1*v1.w + w2*v2.w + w3*v3.w;
    }
    for (; e < e1; e += 4) {          // masked remainder, 4 edges/iter
        int i = e + grp;
        int2 Ee = (i < e1) ? edge[i] : make_int2(0, 0);
        float wt = __int_as_float(Ee.y);          // 0 bits -> 0.0f
        float4 v = tin4[Ee.x * 8 + l];
        a.x += wt * v.x; a.y += wt * v.y; a.z += wt * v.z; a.w += wt * v.w;
    }
#pragma unroll
    for (int d = 8; d <= 16; d <<= 1) {
        a.x += __shfl_xor_sync(0xffffffffu, a.x, d);
        a.y += __shfl_xor_sync(0xffffffffu, a.y, d);
        a.z += __shfl_xor_sync(0xffffffffu, a.z, d);
        a.w += __shfl_xor_sync(0xffffffffu, a.w, d);
    }
    return a;
}

__device__ __forceinline__ float4 elu4(float4 a) {
    a.x = a.x > 0.f ? a.x : (expf(a.x) - 1.f);
    a.y = a.y > 0.f ? a.y : (expf(a.y) - 1.f);
    a.z = a.z > 0.f ? a.z : (expf(a.z) - 1.f);
    a.w = a.w > 0.f ? a.w : (expf(a.w) - 1.f);
    return a;
}

// ---------------------------------------------------------------------------
// Fused layer: tout[n] = (elu(spmm(tin)[n] + b)) @ Wnext
// ---------------------------------------------------------------------------
__global__ void spmm_fused_kernel(const int* __restrict__ off,
                                  const int2* __restrict__ edge,
                                  const float* __restrict__ tin,
                                  const float* __restrict__ b,
                                  const float* __restrict__ W,
                                  float* __restrict__ tout, int N) {
    __shared__ float sW[HDIM * HDIM];
    __shared__ float sb[HDIM];
    int tid = threadIdx.x;
    for (int i = tid; i < HDIM * HDIM; i += blockDim.x) sW[i] = W[i];
    if (tid < HDIM) sb[tid] = b[tid];
    __syncthreads();

    int lane = tid & 31;
    int n = (blockIdx.x * blockDim.x + tid) >> 5;
    if (n >= N) return;

    float4 a = csr_gather(off, edge, (const float4*)tin, n, lane);
    int l = lane & 7;
    float4 vb = *(const float4*)(sb + 4 * l);
    a.x += vb.x; a.y += vb.y; a.z += vb.z; a.w += vb.w;
    a = elu4(a);

    // GEMM 32x32: out[lane] = sum_k h[k]*W[k][lane]; h[4q..4q+3] lives in lane q
    float o = 0.f;
#pragma unroll
    for (int q = 0; q < 8; q++) {
        float hx = __shfl_sync(0xffffffffu, a.x, q);
        float hy = __shfl_sync(0xffffffffu, a.y, q);
        float hz = __shfl_sync(0xffffffffu, a.z, q);
        float hw = __shfl_sync(0xffffffffu, a.w, q);
        o += hx * sW[(4*q+0) * HDIM + lane]
           + hy * sW[(4*q+1) * HDIM + lane]
           + hz * sW[(4*q+2) * HDIM + lane]
           + hw * sW[(4*q+3) * HDIM + lane];
    }
    tout[n * HDIM + lane] = o;
}

// ---------------------------------------------------------------------------
// Final layer fused with pool: pool[seg[n]] += elu(spmm(tin)[n] + b3)
// ---------------------------------------------------------------------------
__global__ void spmm_pool_kernel(const int* __restrict__ off,
                                 const int2* __restrict__ edge,
                                 const float* __restrict__ tin,
                                 const float* __restrict__ b,
                                 const int* __restrict__ seg,
                                 float* __restrict__ pool, int N) {
    __shared__ float sb[HDIM];
    int tid = threadIdx.x;
    if (tid < HDIM) sb[tid] = b[tid];
    __syncthreads();

    int lane = tid & 31;
    int n = (blockIdx.x * blockDim.x + tid) >> 5;
    if (n >= N) return;

    float4 a = csr_gather(off, edge, (const float4*)tin, n, lane);
    int l = lane & 7;
    float4 vb = *(const float4*)(sb + 4 * l);
    a.x += vb.x; a.y += vb.y; a.z += vb.z; a.w += vb.w;
    a = elu4(a);

    if (lane < 8) {
        float4* dst = (float4*)(pool + seg[n] * HDIM) + l;
        asm volatile("red.global.add.v4.f32 [%0], {%1,%2,%3,%4};"
                     :: "l"(__cvta_generic_to_global(dst)),
                        "f"(a.x), "f"(a.y), "f"(a.z), "f"(a.w)
                     : "memory");
    }
}

// ---------------------------------------------------------------------------
// MLP head
// ---------------------------------------------------------------------------
__global__ void mlp_kernel(const float* __restrict__ pool,
                           const float* __restrict__ W1, const float* __restrict__ b1,
                           const float* __restrict__ W2, const float* __restrict__ b2,
                           const float* __restrict__ W3, const float* __restrict__ b3,
                           float* __restrict__ out) {
    __shared__ float sW1[32 * 64], sW2[64 * 32], sW3[32], sb1[64], sb2[32];
    int tid = threadIdx.x;
    for (int i = tid; i < 2048; i += blockDim.x) { sW1[i] = W1[i]; sW2[i] = W2[i]; }
    if (tid < 64) sb1[tid] = b1[tid];
    if (tid < 32) { sW3[tid] = W3[tid]; sb2[tid] = b2[tid]; }
    __syncthreads();

    int g = blockIdx.x * blockDim.x + tid;
    if (g >= NGRAPH) return;
    float in[32];
#pragma unroll
    for (int c = 0; c < 32; c++) in[c] = pool[g * 32 + c];
    float h2[32];
#pragma unroll
    for (int c = 0; c < 32; c++) h2[c] = sb2[c];
    for (int j = 0; j < 64; j++) {
        float t = sb1[j];
#pragma unroll
        for (int c = 0; c < 32; c++) t += in[c] * sW1[c * 64 + j];
        t = fmaxf(t, 0.f);
#pragma unroll
        for (int c = 0; c < 32; c++) h2[c] += t * sW2[j * 32 + c];
    }
    float o = b3[0];
#pragma unroll
    for (int c = 0; c < 32; c++) o += fmaxf(h2[c], 0.f) * sW3[c];
    out[g] = 1.f / (1.f + expf(-o));
}

// ---------------------------------------------------------------------------
extern "C" void kernel_launch(void* const* d_in, const int* in_sizes, int n_in,
                              void* d_out, int out_size) {
    const float* x   = (const float*)d_in[0];
    const int*   ei  = (const int*)  d_in[1];
    const float* ew  = (const float*)d_in[2];
    const int*   seg = (const int*)  d_in[3];
    const float* W1  = (const float*)d_in[4];
    const float* b1  = (const float*)d_in[5];
    const float* W2  = (const float*)d_in[6];
    const float* b2  = (const float*)d_in[7];
    const float* W3  = (const float*)d_in[8];
    const float* b3  = (const float*)d_in[9];
    const float* Wd1 = (const float*)d_in[10];
    const float* bd1 = (const float*)d_in[11];
    const float* Wd2 = (const float*)d_in[12];
    const float* bd2 = (const float*)d_in[13];
    const float* Wd3 = (const float*)d_in[14];
    const float* bd3 = (const float*)d_in[15];
    float* out = (float*)d_out;

    int N = in_sizes[0] / FDIM;
    int E = in_sizes[1] / 2;
    const int* row = ei;
    const int* col = ei + E;

    float *tA, *tB, *pool;
    int *deg, *off, *cursor, *bsum;
    int2 *edge;
    cudaGetSymbolAddress((void**)&tA,     g_tA);
    cudaGetSymbolAddress((void**)&tB,     g_tB);
    cudaGetSymbolAddress((void**)&pool,   g_pool);
    cudaGetSymbolAddress((void**)&deg,    g_deg);
    cudaGetSymbolAddress((void**)&off,    g_off);
    cudaGetSymbolAddress((void**)&cursor, g_cursor);
    cudaGetSymbolAddress((void**)&bsum,   g_bsum);
    cudaGetSymbolAddress((void**)&edge,   g_edge);

    int warpBlocks = (N * 32 + 255) / 256;
    int nb = (N + 1023) / 1024;

    // ---- CSR build (amortized over 3 layers) ----
    cudaMemsetAsync(deg, 0, (size_t)(N + 1) * sizeof(int));
    hist_kernel<<<(E / 4 + 255) / 256 + 1, 256>>>(row, deg, E);
    scan1_kernel<<<nb, 1024>>>(deg, off, bsum, N);
    scan2_kernel<<<1, 128>>>(bsum, nb, off + N);
    scan3_kernel<<<nb, 1024>>>(off, bsum, cursor, N);
    scatter_kernel<<<(E + 255) / 256, 256>>>(row, col, ew, cursor, edge, E);

    // ---- projection + fused GCN layers ----
    gemm1_kernel<<<(N + 31) / 32, 256>>>(x, W1, tA, N);
    spmm_fused_kernel<<<warpBlocks, 256>>>(off, edge, tA, b1, W2, tB, N);
    spmm_fused_kernel<<<warpBlocks, 256>>>(off, edge, tB, b2, W3, tA, N);

    // ---- final layer + pool + head ----
    cudaMemsetAsync(pool, 0, (size_t)NGRAPH * HDIM * sizeof(float));
    spmm_pool_kernel<<<warpBlocks, 256>>>(off, edge, tA, b3, seg, pool, N);
    mlp_kernel<<<2, 256>>>(pool, Wd1, bd1, Wd2, bd2, Wd3, bd3, out);
}